// round 15
// baseline (speedup 1.0000x reference)
#include <cuda_runtime.h>
#include <math.h>

#define Hh 256
#define Ss 64
#define ANa 16
#define Tt 32
#define Nn 64
#define HGg 770   // 2 + 3*H
#define G3 2310   // 3*HG
#define ROW 338   // 1+AN+1+H+S
#define KP 832    // padded GRU K (4*208)
#define XSTEP (KP*Nn)
#define GSTEP (G3*Nn)
#define NTHR 512
#define GRU_GRID 148
#define SCAN_GRID 128
#define TAIL_GRID 128

// ---------------- scratch ----------------
__device__ float g_GIvT[G3 * 32];            // [j'][v]
__device__ float g_GIall[Ss * G3 * Nn];      // [s][j'][n]
__device__ float g_GH[4 * G3 * Nn];          // GRU split-K partials [ks][j'][n]
__device__ float g_whhP[G3 * KP];            // padded w_hh [2310][832]
__device__ float g_Xt[Ss * KP * Nn];         // GRU out k-major [s][j(832)][n]
__device__ float g_Xn[Ss * Nn * HGg];        // [s][n][j]
__device__ float g_MpT[Nn * 256 * 64];       // [n][h][sp]
__device__ float g_MmT[Nn * 256 * 64];
__device__ float g_W0t[2048 * 256];
__device__ float g_linT[256 * 16384];
__device__ float g_psiT[16 * 256 * 256];
__device__ float g_p[Nn * Ss];
__device__ float g_ps[Nn * Ss];
__device__ float g_nMp[Nn * Ss];
__device__ float g_nMm[Nn * Ss];
__device__ float g_r[Nn * 256];
__device__ float g_G[4 * 64 * 2048];         // W0 partials Gt[ks][n][j]
__device__ float g_x0[4096 * 256];
__device__ float g_x1[4096 * 256];
__device__ float g_lp[32 * Nn * 256];        // lin split-K partials [ks][n][o]
__device__ unsigned g_bar1, g_bar2, g_bar3;

// ---------------- sync primitives ----------------
__device__ __forceinline__ unsigned ldacq(unsigned* p)
{
    unsigned v;
    asm volatile("ld.acquire.gpu.u32 %0, [%1];" : "=r"(v) : "l"(p) : "memory");
    return v;
}
__device__ __forceinline__ void redrel(unsigned* p, unsigned v)
{
    asm volatile("red.release.gpu.add.u32 [%0], %1;" :: "l"(p), "r"(v) : "memory");
}
__device__ __forceinline__ void gsync(unsigned* bar, unsigned& target)
{
    __syncthreads();
    if (threadIdx.x == 0) {
        redrel(bar, 1u);
        while (ldacq(bar) < target) __nanosleep(64);
    }
    __syncthreads();
    target += gridDim.x;
}

// ---------------- f32x2 helpers ----------------
typedef unsigned long long ull;
__device__ __forceinline__ void fma2(ull& d, ull a, ull b)
{
    asm("fma.rn.f32x2 %0, %1, %2, %0;" : "+l"(d) : "l"(a), "l"(b));
}
__device__ __forceinline__ float2 unpk(ull v)
{
    unsigned a, b;
    asm("mov.b64 {%0, %1}, %2;" : "=r"(a), "=r"(b) : "l"(v));
    float2 r; r.x = __uint_as_float(a); r.y = __uint_as_float(b);
    return r;
}

// ---------------- shared pools ----------------
struct SP128 { float As[2][16][132]; float Bd[2][16][136]; };
struct SP64  { float As[2][16][68];  float Bd[2][16][136]; };
struct HeadS {
    float s_sm[256]; float e_sm[256]; float red[512]; float red2[512];
    float logit[16]; float probs[16]; float ps_sm[64]; float pn_sm[64];
    float v; float enorm;
};
struct CPool { float bs[512]; float Gs[512]; };
struct TPool { float t1[64][65]; float t2[64][65]; };
struct StepA { float pv[64]; float psv[64]; };
union SUscan { SP128 g; SP64 g64; HeadS h; CPool c; };
union SUtail { TPool t; StepA a; };

// ================= 128x64 tile GEMM, dup-B FFMA2, 512 threads =================
// C = A[m0:+128, kb:+kc] . B^T ; B [N][ldb] row-major. Exact tiles.
__device__ void tile128(SP128& sp,
                        const float* __restrict__ A, int lda,
                        const float* __restrict__ B, int ldb,
                        float* __restrict__ C, int ldc,
                        int m0, int n0, int kb, int kc,
                        const float* __restrict__ bias, bool relu)
{
    const int tid = threadIdx.x;
    const int am = tid >> 2, ak4 = (tid & 3) * 4;
    const int bn = tid >> 3, bk2 = (tid & 7) * 2;
    const int ty = tid >> 4, tx = tid & 15;          // ty 0..31, rows ty*4..+3
    const int nk = kc >> 4;
    float4 pa; float2 pb;

    auto ldg = [&](int kt) {
        int k0 = kb + kt * 16;
        pa = *(const float4*)(A + (size_t)(m0 + am) * lda + k0 + ak4);
        pb = *(const float2*)(B + (size_t)(n0 + bn) * ldb + k0 + bk2);
    };
    auto sts = [&](int buf) {
        sp.As[buf][ak4 + 0][am] = pa.x; sp.As[buf][ak4 + 1][am] = pa.y;
        sp.As[buf][ak4 + 2][am] = pa.z; sp.As[buf][ak4 + 3][am] = pa.w;
        *(float2*)&sp.Bd[buf][bk2][bn * 2]     = make_float2(pb.x, pb.x);
        *(float2*)&sp.Bd[buf][bk2 + 1][bn * 2] = make_float2(pb.y, pb.y);
    };

    ull acc[2][4];
    #pragma unroll
    for (int i = 0; i < 2; i++)
        #pragma unroll
        for (int j = 0; j < 4; j++) acc[i][j] = 0ULL;

    ldg(0); sts(0); __syncthreads();
    for (int kt = 0; kt < nk; kt++) {
        if (kt + 1 < nk) ldg(kt + 1);
        const int buf = kt & 1;
        #pragma unroll
        for (int kk = 0; kk < 16; kk++) {
            ull a0 = *(const ull*)&sp.As[buf][kk][ty * 4];
            ull a1 = *(const ull*)&sp.As[buf][kk][ty * 4 + 2];
            ulonglong2 b01 = *(const ulonglong2*)&sp.Bd[buf][kk][tx * 8];
            ulonglong2 b23 = *(const ulonglong2*)&sp.Bd[buf][kk][tx * 8 + 4];
            fma2(acc[0][0], a0, b01.x); fma2(acc[0][1], a0, b01.y);
            fma2(acc[0][2], a0, b23.x); fma2(acc[0][3], a0, b23.y);
            fma2(acc[1][0], a1, b01.x); fma2(acc[1][1], a1, b01.y);
            fma2(acc[1][2], a1, b23.x); fma2(acc[1][3], a1, b23.y);
        }
        if (kt + 1 < nk) sts(buf ^ 1);
        __syncthreads();
    }

    int gn = n0 + tx * 4;
    float4 bv = make_float4(0.f, 0.f, 0.f, 0.f);
    if (bias) bv = make_float4(bias[gn], bias[gn + 1], bias[gn + 2], bias[gn + 3]);
    #pragma unroll
    for (int i = 0; i < 2; i++) {
        float2 c0 = unpk(acc[i][0]), c1 = unpk(acc[i][1]);
        float2 c2 = unpk(acc[i][2]), c3 = unpk(acc[i][3]);
        float4 r0 = make_float4(c0.x + bv.x, c1.x + bv.y, c2.x + bv.z, c3.x + bv.w);
        float4 r1 = make_float4(c0.y + bv.x, c1.y + bv.y, c2.y + bv.z, c3.y + bv.w);
        if (relu) {
            r0.x = fmaxf(r0.x,0.f); r0.y = fmaxf(r0.y,0.f); r0.z = fmaxf(r0.z,0.f); r0.w = fmaxf(r0.w,0.f);
            r1.x = fmaxf(r1.x,0.f); r1.y = fmaxf(r1.y,0.f); r1.z = fmaxf(r1.z,0.f); r1.w = fmaxf(r1.w,0.f);
        }
        int gm = m0 + ty * 4 + 2 * i;
        *(float4*)&C[(size_t)gm * ldc + gn] = r0;
        *(float4*)&C[(size_t)(gm + 1) * ldc + gn] = r1;
    }
    __syncthreads();
}

// ================= 64x64 tile, dup-B, B k-major [K][64], 512 thr (GRU) =================
__device__ void tile64k(SP64& sp,
                        const float* __restrict__ A, int lda,
                        const float* __restrict__ B,
                        float* __restrict__ C, int ldc,
                        int M, int m0, int kb, int kc)
{
    const int tid = threadIdx.x;
    const int am = tid >> 3, ak2 = (tid & 7) * 2;
    const int bk = tid >> 5, bn2 = (tid & 31) * 2;
    const int ty = tid >> 4, tx = tid & 15;          // rows ty*2, cols tx*4
    const int nk = kc >> 4;
    const float2 z2 = make_float2(0.f, 0.f);
    float2 pa, pb;

    auto ldg = [&](int kt) {
        int k0 = kb + kt * 16;
        pa = (m0 + am < M) ? *(const float2*)(A + (size_t)(m0 + am) * lda + k0 + ak2) : z2;
        pb = *(const float2*)(B + (size_t)(k0 + bk) * 64 + bn2);
    };
    auto sts = [&](int buf) {
        sp.As[buf][ak2 + 0][am] = pa.x;
        sp.As[buf][ak2 + 1][am] = pa.y;
        *(float4*)&sp.Bd[buf][bk][bn2 * 2] = make_float4(pb.x, pb.x, pb.y, pb.y);
    };

    ull acc[4];
    #pragma unroll
    for (int j = 0; j < 4; j++) acc[j] = 0ULL;

    ldg(0); sts(0); __syncthreads();
    for (int kt = 0; kt < nk; kt++) {
        if (kt + 1 < nk) ldg(kt + 1);
        const int buf = kt & 1;
        #pragma unroll
        for (int kk = 0; kk < 16; kk++) {
            ull a = *(const ull*)&sp.As[buf][kk][ty * 2];
            ulonglong2 b01 = *(const ulonglong2*)&sp.Bd[buf][kk][tx * 8];
            ulonglong2 b23 = *(const ulonglong2*)&sp.Bd[buf][kk][tx * 8 + 4];
            fma2(acc[0], a, b01.x); fma2(acc[1], a, b01.y);
            fma2(acc[2], a, b23.x); fma2(acc[3], a, b23.y);
        }
        if (kt + 1 < nk) sts(buf ^ 1);
        __syncthreads();
    }

    int gn = tx * 4;
    float2 c0 = unpk(acc[0]), c1 = unpk(acc[1]);
    float2 c2 = unpk(acc[2]), c3 = unpk(acc[3]);
    int gm = m0 + ty * 2;
    if (gm < M)
        *(float4*)&C[(size_t)gm * ldc + gn] = make_float4(c0.x, c1.x, c2.x, c3.x);
    if (gm + 1 < M)
        *(float4*)&C[(size_t)(gm + 1) * ldc + gn] = make_float4(c0.y, c1.y, c2.y, c3.y);
    __syncthreads();
}

// ================= 64x64 tile, dup-B, A fixed 64 rows, B [N][ldb], 512 thr =================
__device__ void tile64n(SP64& sp,
                        const float* __restrict__ A, int lda,
                        const float* __restrict__ B, int ldb,
                        float* __restrict__ C, int ldc,
                        int n0, int kb, int kc)
{
    const int tid = threadIdx.x;
    const int am = tid >> 3, ak2 = (tid & 7) * 2;
    const int bn = tid >> 3, bk2 = (tid & 7) * 2;
    const int ty = tid >> 4, tx = tid & 15;
    const int nk = kc >> 4;
    float2 pa, pb;

    auto ldg = [&](int kt) {
        int k0 = kb + kt * 16;
        pa = *(const float2*)(A + (size_t)am * lda + k0 + ak2);
        pb = *(const float2*)(B + (size_t)(n0 + bn) * ldb + k0 + bk2);
    };
    auto sts = [&](int buf) {
        sp.As[buf][ak2 + 0][am] = pa.x;
        sp.As[buf][ak2 + 1][am] = pa.y;
        *(float2*)&sp.Bd[buf][bk2][bn * 2]     = make_float2(pb.x, pb.x);
        *(float2*)&sp.Bd[buf][bk2 + 1][bn * 2] = make_float2(pb.y, pb.y);
    };

    ull acc[4];
    #pragma unroll
    for (int j = 0; j < 4; j++) acc[j] = 0ULL;

    ldg(0); sts(0); __syncthreads();
    for (int kt = 0; kt < nk; kt++) {
        if (kt + 1 < nk) ldg(kt + 1);
        const int buf = kt & 1;
        #pragma unroll
        for (int kk = 0; kk < 16; kk++) {
            ull a = *(const ull*)&sp.As[buf][kk][ty * 2];
            ulonglong2 b01 = *(const ulonglong2*)&sp.Bd[buf][kk][tx * 8];
            ulonglong2 b23 = *(const ulonglong2*)&sp.Bd[buf][kk][tx * 8 + 4];
            fma2(acc[0], a, b01.x); fma2(acc[1], a, b01.y);
            fma2(acc[2], a, b23.x); fma2(acc[3], a, b23.y);
        }
        if (kt + 1 < nk) sts(buf ^ 1);
        __syncthreads();
    }

    int gn = n0 + tx * 4;
    float2 c0 = unpk(acc[0]), c1 = unpk(acc[1]);
    float2 c2 = unpk(acc[2]), c3 = unpk(acc[3]);
    int gm = ty * 2;
    *(float4*)&C[(size_t)gm * ldc + gn] = make_float4(c0.x, c1.x, c2.x, c3.x);
    *(float4*)&C[(size_t)(gm + 1) * ldc + gn] = make_float4(c0.y, c1.y, c2.y, c3.y);
    __syncthreads();
}

// ---------------- prep: barrier reset + all weight re-layouts (256 thr) ----------------
#define EW0 524288    // W0t
#define EW1 4194304   // linT
#define EW2 1048576   // psiT
#define EW3 1921920   // whhP
#define EW4 253952    // Xt pad zero
#define EWT (EW0+EW1+EW2+EW3+EW4)

__global__ void prep(const float* __restrict__ conv0_w, const float* __restrict__ lin_w,
                     const float* __restrict__ psi_w, const float* __restrict__ w_hh,
                     float* __restrict__ W0t, float* __restrict__ linT,
                     float* __restrict__ psiT, float* __restrict__ whhP,
                     float* __restrict__ Xt)
{
    const int tid = threadIdx.x;
    if (blockIdx.x == 0 && tid < 3) {
        if (tid == 0) g_bar1 = 0;
        else if (tid == 1) g_bar2 = 0;
        else g_bar3 = 0;
    }
    int idx = blockIdx.x * 256 + tid;
    const int stride = gridDim.x * 256;
    for (; idx < EWT; idx += stride) {
        int e = idx;
        if (e < EW0) {
            int h = e & 255, j = e >> 8;
            int o = j >> 3, d = j & 7;
            W0t[e] = conv0_w[o * 2048 + h * 8 + d];
        } else if ((e -= EW0) < EW1) {
            int c = e & 255, pp = (e >> 8) & 63, o = e >> 14;
            linT[e] = lin_w[(size_t)o * 16384 + c * 64 + pp];
        } else if ((e -= EW1) < EW2) {
            int o = e & 255, h = (e >> 8) & 255, a = e >> 16;
            psiT[e] = psi_w[(size_t)o * 4096 + h * 16 + a];
        } else if ((e -= EW2) < EW3) {
            int k = e % KP, j = e / KP;
            whhP[e] = (k < HGg) ? w_hh[j * HGg + k] : 0.f;
        } else {
            e -= EW3;
            int n = e & 63, jj = (e >> 6) % (KP - HGg), s = e / ((KP - HGg) * Nn);
            Xt[(size_t)s * XSTEP + (size_t)(HGg + jj) * 64 + n] = 0.f;
        }
    }
}

// =========== standalone SGEMM (GIvT only, 256 thr) ===========
__global__ void __launch_bounds__(256, 2)
sg(const float* __restrict__ A, int lda,
   const float* __restrict__ B, int ldb,
   float* __restrict__ C, int M, int N, int K)
{
    __shared__ float As[2][16][132];
    __shared__ float Bs[2][16][68];
    const int tid = threadIdx.x;
    const int m0 = blockIdx.x * 128;
    const int nk = K >> 4;
    const int am = tid >> 1, ak = (tid & 1) * 8;
    const int bn = tid >> 2, bk4 = (tid & 3) * 4;
    const int ty = tid >> 4, tx = tid & 15;
    float4 pa0, pa1, pb;
    const float4 z4 = make_float4(0.f, 0.f, 0.f, 0.f);

    auto ldg = [&](int kt) {
        int k0 = kt * 16;
        if (m0 + am < M) {
            const float* ap = A + (size_t)(m0 + am) * lda + k0 + ak;
            pa0 = *(const float4*)ap;
            pa1 = *(const float4*)(ap + 4);
        } else { pa0 = z4; pa1 = z4; }
        pb = (bn < N) ? *(const float4*)(B + (size_t)bn * ldb + k0 + bk4) : z4;
    };
    auto sts = [&](int buf) {
        As[buf][ak + 0][am] = pa0.x; As[buf][ak + 1][am] = pa0.y;
        As[buf][ak + 2][am] = pa0.z; As[buf][ak + 3][am] = pa0.w;
        As[buf][ak + 4][am] = pa1.x; As[buf][ak + 5][am] = pa1.y;
        As[buf][ak + 6][am] = pa1.z; As[buf][ak + 7][am] = pa1.w;
        Bs[buf][bk4 + 0][bn] = pb.x; Bs[buf][bk4 + 1][bn] = pb.y;
        Bs[buf][bk4 + 2][bn] = pb.z; Bs[buf][bk4 + 3][bn] = pb.w;
    };

    float acc[8][4];
    #pragma unroll
    for (int i = 0; i < 8; i++)
        #pragma unroll
        for (int j = 0; j < 4; j++) acc[i][j] = 0.f;

    ldg(0); sts(0); __syncthreads();
    for (int kt = 0; kt < nk; kt++) {
        if (kt + 1 < nk) ldg(kt + 1);
        const int buf = kt & 1;
        #pragma unroll
        for (int kk = 0; kk < 16; kk++) {
            float4 a0 = *(const float4*)&As[buf][kk][ty * 8];
            float4 a1 = *(const float4*)&As[buf][kk][ty * 8 + 4];
            float4 b  = *(const float4*)&Bs[buf][kk][tx * 4];
            float av[8] = {a0.x, a0.y, a0.z, a0.w, a1.x, a1.y, a1.z, a1.w};
            float bv[4] = {b.x, b.y, b.z, b.w};
            #pragma unroll
            for (int i = 0; i < 8; i++)
                #pragma unroll
                for (int j = 0; j < 4; j++) acc[i][j] += av[i] * bv[j];
        }
        if (kt + 1 < nk) sts(buf ^ 1);
        __syncthreads();
    }
    #pragma unroll
    for (int i = 0; i < 8; i++) {
        int gm = m0 + ty * 8 + i;
        if (gm >= M) continue;
        int gn = tx * 4;
        #pragma unroll
        for (int j = 0; j < 4; j++)
            if (gn + j < N) C[(size_t)gm * N + gn + j] = acc[i][j];
    }
}

__global__ void gather_gi(const float* __restrict__ GIvT, const int* __restrict__ subtasks,
                          float* __restrict__ GIall)
{
    int s = blockIdx.x;
    int idx = blockIdx.y * 256 + threadIdx.x;
    if (idx >= G3 * 64) return;
    int jp = idx >> 6, n = idx & 63;
    int v = subtasks[n * Ss + s];
    GIall[(size_t)s * GSTEP + idx] = GIvT[jp * 32 + v];
}

// ---------------- persistent GRU (barrier form, 512 thr) ----------------
__global__ void __launch_bounds__(NTHR, 1)
gru_persist(const float* __restrict__ whhP, const float* __restrict__ GIall,
            const float* __restrict__ b_ih, const float* __restrict__ b_hh,
            float* __restrict__ GH, float* __restrict__ Xt)
{
    __shared__ SP64 sp;
    unsigned target = gridDim.x;
    const int bid = blockIdx.x;
    const int tid = threadIdx.x;
    for (int s = 0; s < Ss; s++) {
        if (s > 0) {
            int mt = bid % 37, ks = bid / 37;
            tile64k(sp, whhP, KP, Xt + (size_t)(s - 1) * XSTEP,
                    GH + (size_t)ks * GSTEP, 64, G3, mt * 64, ks * 208, 208);
            gsync(&g_bar1, target);
        }
        for (int idx = bid * NTHR + tid; idx < HGg * Nn; idx += gridDim.x * NTHR) {
            int j = idx >> 6, n = idx & 63;
            const float* gia = GIall + (size_t)s * GSTEP;
            float gir = gia[(size_t)j * 64 + n]             + b_ih[j];
            float giz = gia[(size_t)(j + HGg) * 64 + n]     + b_ih[HGg + j];
            float gin = gia[(size_t)(j + 2 * HGg) * 64 + n] + b_ih[2 * HGg + j];
            float ghr = b_hh[j], ghz = b_hh[HGg + j], ghn = b_hh[2 * HGg + j];
            float hprev = 0.f;
            if (s > 0) {
                #pragma unroll
                for (int ks = 0; ks < 4; ks++) {
                    const float* g = GH + (size_t)ks * GSTEP;
                    ghr += g[(size_t)j * 64 + n];
                    ghz += g[(size_t)(j + HGg) * 64 + n];
                    ghn += g[(size_t)(j + 2 * HGg) * 64 + n];
                }
                hprev = Xt[(size_t)(s - 1) * XSTEP + (size_t)j * 64 + n];
            }
            float r = 1.f / (1.f + expf(-(gir + ghr)));
            float z = 1.f / (1.f + expf(-(giz + ghz)));
            float nn = tanhf(gin + r * ghn);
            Xt[(size_t)s * XSTEP + (size_t)j * 64 + n] = (1.f - z) * nn + z * hprev;
        }
        gsync(&g_bar1, target);
    }
}

// ---------------- tail (256 thr) ----------------
__global__ void __launch_bounds__(256, 1)
tail_kernel(const float* __restrict__ Xt, const float* __restrict__ hxs,
            float* __restrict__ Xn, float* __restrict__ MpT, float* __restrict__ MmT,
            float* __restrict__ nMp, float* __restrict__ nMm,
            float* __restrict__ p, float* __restrict__ ps, float* __restrict__ r)
{
    __shared__ SUtail su;
    __shared__ int anynz;
    unsigned target = gridDim.x;
    const int bid = blockIdx.x;
    const int tid = threadIdx.x;

    for (int job = bid; job < Ss * 13; job += gridDim.x) {
        int s = job / 13, j0 = (job % 13) * 64;
        for (int pq = 0; pq < 16; pq++) {
            int e = pq * 256 + tid;
            int jj = e >> 6, nn = e & 63;
            if (j0 + jj < HGg)
                su.t.t1[jj][nn] = Xt[(size_t)s * XSTEP + (size_t)(j0 + jj) * 64 + nn];
        }
        __syncthreads();
        for (int pq = 0; pq < 16; pq++) {
            int e = pq * 256 + tid;
            int nn = e >> 6, jj = e & 63;
            if (j0 + jj < HGg)
                Xn[(size_t)(s * Nn + nn) * HGg + j0 + jj] = su.t.t1[jj][nn];
        }
        __syncthreads();
    }
    gsync(&g_bar3, target);

    for (int job = bid; job < 256; job += gridDim.x) {
        int n = job >> 2, h0 = (job & 3) * 64;
        for (int pq = 0; pq < 16; pq++) {
            int e = pq * 256 + tid;
            int sp = e >> 6, h = e & 63;
            const float* row = Xn + (size_t)(sp * Nn + n) * HGg;
            su.t.t1[sp][h] = row[2 + 2 * Hh + h0 + h];
            su.t.t2[sp][h] = row[2 + Hh + h0 + h];
        }
        __syncthreads();
        for (int pq = 0; pq < 16; pq++) {
            int e = pq * 256 + tid;
            int h = e >> 6, sp = e & 63;
            MpT[((size_t)n * 256 + h0 + h) * 64 + sp] = su.t.t1[sp][h];
            MmT[((size_t)n * 256 + h0 + h) * 64 + sp] = su.t.t2[sp][h];
        }
        __syncthreads();
    }
    if (bid < 64) {
        const int n = bid;
        if (tid == 0) anynz = 0;
        __syncthreads();
        int local = 0;
        for (int i = tid; i < ROW; i += 256)
            if (hxs[n * ROW + i] != 0.f) local = 1;
        if (local) atomicOr(&anynz, 1);
        __syncthreads();
        bool newep = (anynz == 0);
        if (tid < Ss) {
            float p0 = Xn[(size_t)(tid * Nn + n) * HGg + 1];
            p[n * Ss + tid] = newep ? p0 : hxs[n * ROW + 1 + ANa + 1 + Hh + tid];
        }
    }
    gsync(&g_bar3, target);

    if (bid < 16) {
        int idx = bid * 256 + tid;
        int n = idx >> 6, sp = idx & 63;
        const float* bp = MpT + (size_t)n * 256 * 64 + sp;
        const float* bm = MmT + (size_t)n * 256 * 64 + sp;
        float ap = 0.f, am = 0.f;
        #pragma unroll 8
        for (int h = 0; h < 256; h++) {
            float x = bp[h * 64]; ap += x * x;
            float y = bm[h * 64]; am += y * y;
        }
        nMp[idx] = sqrtf(ap);
        nMm[idx] = sqrtf(am);
    } else if (bid >= 64) {
        const int n = bid - 64;
        if (tid < 64) su.a.pv[tid] = p[n * 64 + tid];
        __syncthreads();
        if (tid == 0) {
            float m = su.a.pv[0];
            for (int i = 1; i < 64; i++) m = fmaxf(m, su.a.pv[i]);
            float sum = 0.f;
            for (int i = 0; i < 64; i++) { float e = expf(su.a.pv[i] - m); su.a.psv[i] = e; sum += e; }
            float inv = 1.f / sum;
            for (int i = 0; i < 64; i++) su.a.psv[i] *= inv;
        }
        __syncthreads();
        if (tid < 64) ps[n * 64 + tid] = su.a.psv[tid];
        float acc = 0.f;
        for (int s = 0; s < 64; s++)
            acc += su.a.psv[s] * Xn[(size_t)(s * Nn + n) * HGg + 2 + tid];
        r[n * 256 + tid] = acc;
    }
}

// ---------------- head body (512 threads) ----------------
__device__ void head_body(HeadS& hs, int n,
    const float* __restrict__ lp, const float* __restrict__ lin_b,
    float* __restrict__ ps_buf,
    const float* __restrict__ X, const float* __restrict__ MpT, const float* __restrict__ MmT,
    const float* __restrict__ nMp, const float* __restrict__ nMm,
    const float* __restrict__ psiT, const float* __restrict__ psi_b,
    const float* __restrict__ actor_w, const float* __restrict__ actor_b,
    const float* __restrict__ critic_w, const float* __restrict__ critic_b,
    const float* __restrict__ inter_t, const int* __restrict__ act_t,
    float* __restrict__ r_out, float* __restrict__ out_t)
{
    const int tid = threadIdx.x;
    if (tid < 256) {
        float sv = lin_b[tid];
        #pragma unroll 4
        for (int ks = 0; ks < 32; ks++) sv += lp[(size_t)ks * 16384 + n * 256 + tid];
        hs.s_sm[tid] = fmaxf(sv, 0.f);
    }
    if (tid < 64) hs.ps_sm[tid] = ps_buf[n * 64 + tid];
    __syncthreads();
    int a = act_t[n];
    // psi: split over 2 halves of h
    {
        int o = tid & 255, half = tid >> 8;
        float acc = 0.f;
        const float* P = psiT + (size_t)a * 65536 + (size_t)half * 128 * 256;
        const float* sh = hs.s_sm + half * 128;
        for (int h = 0; h < 128; h++) acc += P[h * 256 + o] * sh[h];
        hs.red[tid] = acc;
    }
    __syncthreads();
    if (tid < 256) {
        float e = hs.red[tid] + hs.red[tid + 256] + psi_b[tid];
        hs.e_sm[tid] = e;
        hs.red2[tid] = e * e;
    }
    __syncthreads();
    for (int off = 128; off > 0; off >>= 1) {
        if (tid < off) hs.red2[tid] += hs.red2[tid + off];
        __syncthreads();
    }
    if (tid == 0) hs.enorm = sqrtf(hs.red2[0]);
    if (tid < 16) {
        float acc = actor_b[tid];
        for (int h = 0; h < 256; h++) acc += actor_w[tid * 256 + h] * hs.s_sm[h];
        hs.logit[tid] = acc;
    } else if (tid == 32) {
        float acc = critic_b[0];
        for (int h = 0; h < 256; h++) acc += critic_w[h] * hs.s_sm[h];
        hs.v = acc;
    }
    __syncthreads();
    if (tid == 0) {
        float pr[16], nonzero[16];
        float mx = hs.logit[0];
        for (int aa = 1; aa < 16; aa++) mx = fmaxf(mx, hs.logit[aa]);
        float sum = 0.f;
        for (int aa = 0; aa < 16; aa++) { pr[aa] = expf(hs.logit[aa] - mx); sum += pr[aa]; }
        float inv = 1.f / sum;
        float nzsum = 0.f;
        for (int aa = 0; aa < 16; aa++) {
            float nz = (aa < 5) ? 1.f : inter_t[n * 11 + aa - 5];
            nonzero[aa] = nz; nzsum += fabsf(nz);
        }
        float psum = 0.f;
        for (int aa = 0; aa < 16; aa++) { pr[aa] = pr[aa] * inv * nonzero[aa]; psum += pr[aa]; }
        float deficit = 1.f - psum;
        float nzinv = 1.f / fmaxf(nzsum, 1e-12f);
        float csum = 0.f;
        for (int aa = 0; aa < 16; aa++) {
            float v2 = pr[aa] + nonzero[aa] * nzinv * deficit;
            v2 = fminf(fmaxf(v2, 0.f), 1.f);
            pr[aa] = v2; csum += fabsf(v2);
        }
        float cinv = 1.f / fmaxf(csum, 1e-12f);
        for (int aa = 0; aa < 16; aa++) hs.probs[aa] = pr[aa] * cinv;
    }
    __syncthreads();
    // cosine numerators: 8 h-chunks x 64 sp over 512 threads
    {
        int sp = tid & 63, hq = tid >> 6;
        const float* bp = MpT + ((size_t)n * 256 + hq * 32) * 64 + sp;
        const float* bm = MmT + ((size_t)n * 256 + hq * 32) * 64 + sp;
        float np = 0.f, nm = 0.f;
        #pragma unroll 8
        for (int h = 0; h < 32; h++) {
            float e = hs.e_sm[hq * 32 + h];
            np += e * bp[h * 64];
            nm += e * bm[h * 64];
        }
        hs.red[tid] = np; hs.red2[tid] = nm;
    }
    __syncthreads();
    if (tid < 64) {
        int sp = tid;
        float np = 0.f, nm = 0.f;
        #pragma unroll
        for (int q = 0; q < 8; q++) { np += hs.red[q * 64 + sp]; nm += hs.red2[q * 64 + sp]; }
        float en = hs.enorm;
        float c = X[(size_t)(sp * Nn + n) * HGg];
        float cosp = np / fmaxf(en * nMp[n * 64 + sp], 1e-8f);
        float cosm = nm / fmaxf(en * nMm[n * 64 + sp], 1e-8f);
        float pn = hs.ps_sm[sp] + c * cosp - c * cosm;
        hs.pn_sm[sp] = pn;
        out_t[(size_t)n * ROW + 1 + ANa + 1 + Hh + sp] = pn;
    }
    if (tid < 256) out_t[(size_t)n * ROW + 18 + tid] = hs.s_sm[tid];
    if (tid < 16) out_t[(size_t)n * ROW + 1 + tid] = hs.probs[tid];
    if (tid == 0) {
        out_t[(size_t)n * ROW + 0] = (float)a;
        out_t[(size_t)n * ROW + 17] = hs.v;
    }
    __syncthreads();
    if (tid == 0) {
        float m = hs.pn_sm[0];
        for (int i = 1; i < 64; i++) m = fmaxf(m, hs.pn_sm[i]);
        float sum = 0.f;
        for (int i = 0; i < 64; i++) { float e = expf(hs.pn_sm[i] - m); hs.ps_sm[i] = e; sum += e; }
        float inv = 1.f / sum;
        for (int i = 0; i < 64; i++) hs.ps_sm[i] *= inv;
    }
    __syncthreads();
    if (tid < 64) ps_buf[n * 64 + tid] = hs.ps_sm[tid];
    if (tid < 256) {
        float acc = 0.f;
        for (int s = 0; s < 64; s++)
            acc += hs.ps_sm[s] * X[(size_t)(s * Nn + n) * HGg + 2 + tid];
        r_out[n * 256 + tid] = acc;
    }
    __syncthreads();
}

// ---------------- persistent scan (128 blocks x 512 thr) ----------------
__global__ void __launch_bounds__(NTHR, 1)
scan_persist(const float* __restrict__ W0t, const float* __restrict__ base,
             const float* __restrict__ conv0_b,
             const float* __restrict__ convs_w, const float* __restrict__ convs_b,
             const float* __restrict__ linT, const float* __restrict__ lin_b,
             const float* __restrict__ Xn, const float* __restrict__ MpT,
             const float* __restrict__ MmT,
             const float* __restrict__ nMp, const float* __restrict__ nMm,
             const float* __restrict__ psiT, const float* __restrict__ psi_b,
             const float* __restrict__ actor_w, const float* __restrict__ actor_b,
             const float* __restrict__ critic_w, const float* __restrict__ critic_b,
             const float* __restrict__ inter, const int* __restrict__ actions,
             float* __restrict__ G, float* __restrict__ x0, float* __restrict__ x1,
             float* __restrict__ lp, float* __restrict__ ps, float* __restrict__ r,
             float* __restrict__ out)
{
    __shared__ SUscan su;
    unsigned target = gridDim.x;
    const int bid = blockIdx.x;
    const int tid = threadIdx.x;

    for (int t = 0; t < Tt; t++) {
        // P1: Gt[ks][n][j] = r . W0t^T  (32 jt x 4 ks)
        {
            int jt = bid & 31, ks = bid >> 5;
            tile64n(su.g64, r, 256, W0t, 256,
                    G + (size_t)ks * 64 * 2048, 2048, jt * 64, ks * 64, 64);
        }
        gsync(&g_bar2, target);

        // P2: conv0 dot-8 collapse -> x0[(n*64+p)][o]
        const float* base_t = base + (size_t)t * Nn * 512;
        for (int job = bid; job < 256; job += gridDim.x) {
            int n = job >> 2, o0 = (job & 3) * 64;
            for (int e = tid; e < 512; e += NTHR) su.c.bs[e] = base_t[n * 512 + e];
            for (int e = tid; e < 512; e += NTHR) {
                int j = o0 * 8 + e;
                float v = 0.f;
                #pragma unroll
                for (int ks = 0; ks < 4; ks++) v += G[(size_t)ks * 131072 + n * 2048 + j];
                su.c.Gs[e] = v;
            }
            __syncthreads();
            int o_l = tid & 63;
            int pg = tid >> 6;                    // 0..7
            float bias = conv0_b[o0 + o_l];
            for (int k = 0; k < 8; k++) {
                int pp = pg * 8 + k;
                float acc = bias;
                #pragma unroll
                for (int d = 0; d < 8; d++) acc += su.c.Gs[o_l * 8 + d] * su.c.bs[d * 64 + pp];
                x0[((size_t)n * 64 + pp) * 256 + o0 + o_l] = fmaxf(acc, 0.f);
            }
            __syncthreads();
        }
        gsync(&g_bar2, target);

        // P3: conv1 (32 mt x 4 nt)
        {
            int mt = bid >> 2, nt = bid & 3;
            tile128(su.g, x0, 256, convs_w, 256, x1, 256,
                    mt * 128, nt * 64, 0, 256, convs_b, true);
        }
        gsync(&g_bar2, target);

        // P4: conv2
        {
            int mt = bid >> 2, nt = bid & 3;
            tile128(su.g, x1, 256, convs_w + 65536, 256, x0, 256,
                    mt * 128, nt * 64, 0, 256, convs_b + 256, true);
        }
        gsync(&g_bar2, target);

        // P5: lin partials lp[ks][64][256]  (4 nt x 32 ks)
        {
            int nt = bid & 3, ks = bid >> 2;
            tile64n(su.g64, x0, 16384, linT, 16384,
                    lp + (size_t)ks * 16384, 256, nt * 64, ks * 512, 512);
        }
        gsync(&g_bar2, target);

        // P6: head (folds lin reduce)
        if (bid < 64) {
            head_body(su.h, bid, lp, lin_b, ps, Xn, MpT, MmT, nMp, nMm,
                      psiT, psi_b, actor_w, actor_b, critic_w, critic_b,
                      inter + (size_t)t * Nn * 11, actions + t * Nn,
                      r, out + (size_t)t * Nn * ROW);
        }
        gsync(&g_bar2, target);
    }
}

__global__ void copy_last(float* __restrict__ out, int out_size)
{
    int idx = blockIdx.x * 256 + threadIdx.x;
    if (idx >= Nn * ROW) return;
    int dst = Tt * Nn * ROW + idx;
    if (dst < out_size) out[dst] = out[(Tt - 1) * Nn * ROW + idx];
}

// ---------------- orchestration ----------------
extern "C" void kernel_launch(void* const* d_in, const int* in_sizes, int n_in,
                              void* d_out, int out_size)
{
    const float* base    = (const float*)d_in[0];
    const float* inter   = (const float*)d_in[1];
    const float* hxs     = (const float*)d_in[2];
    const float* emb     = (const float*)d_in[3];
    const float* w_ih    = (const float*)d_in[4];
    const float* w_hh    = (const float*)d_in[5];
    const float* b_ih    = (const float*)d_in[6];
    const float* b_hh    = (const float*)d_in[7];
    const float* conv0_w = (const float*)d_in[8];
    const float* conv0_b = (const float*)d_in[9];
    const float* convs_w = (const float*)d_in[10];
    const float* convs_b = (const float*)d_in[11];
    const float* lin_w   = (const float*)d_in[12];
    const float* lin_b   = (const float*)d_in[13];
    const float* psi_w   = (const float*)d_in[14];
    const float* psi_b   = (const float*)d_in[15];
    const float* actor_w = (const float*)d_in[16];
    const float* actor_b = (const float*)d_in[17];
    const float* critic_w= (const float*)d_in[18];
    const float* critic_b= (const float*)d_in[19];
    const int*   subtasks= (const int*)d_in[20];
    const int*   actions = (const int*)d_in[21];
    float* out = (float*)d_out;

    float *GIvT, *GIall, *GH, *whhP, *Xt, *Xn, *MpT, *MmT, *W0t, *linT, *psiT;
    float *p, *ps, *nMp, *nMm, *r, *G, *x0, *x1, *lp;
    cudaGetSymbolAddress((void**)&GIvT,  g_GIvT);
    cudaGetSymbolAddress((void**)&GIall, g_GIall);
    cudaGetSymbolAddress((void**)&GH,    g_GH);
    cudaGetSymbolAddress((void**)&whhP,  g_whhP);
    cudaGetSymbolAddress((void**)&Xt,    g_Xt);
    cudaGetSymbolAddress((void**)&Xn,    g_Xn);
    cudaGetSymbolAddress((void**)&MpT,   g_MpT);
    cudaGetSymbolAddress((void**)&MmT,   g_MmT);
    cudaGetSymbolAddress((void**)&W0t,   g_W0t);
    cudaGetSymbolAddress((void**)&linT,  g_linT);
    cudaGetSymbolAddress((void**)&psiT,  g_psiT);
    cudaGetSymbolAddress((void**)&p,     g_p);
    cudaGetSymbolAddress((void**)&ps,    g_ps);
    cudaGetSymbolAddress((void**)&nMp,   g_nMp);
    cudaGetSymbolAddress((void**)&nMm,   g_nMm);
    cudaGetSymbolAddress((void**)&r,     g_r);
    cudaGetSymbolAddress((void**)&G,     g_G);
    cudaGetSymbolAddress((void**)&x0,    g_x0);
    cudaGetSymbolAddress((void**)&x1,    g_x1);
    cudaGetSymbolAddress((void**)&lp,    g_lp);

    // 1: prep (barrier reset + all weight re-layouts)
    prep<<<2048, 256>>>(conv0_w, lin_w, psi_w, w_hh, W0t, linT, psiT, whhP, Xt);
    // 2: GIvT GEMM
    sg<<<19, 256>>>(w_ih, 256, emb, 256, GIvT, G3, 32, 256);
    // 3: gather input gates
    gather_gi<<<dim3(Ss, (G3 * 64 + 255) / 256), 256>>>(GIvT, subtasks, GIall);
    // 4: persistent GRU (512 thr)
    gru_persist<<<GRU_GRID, NTHR>>>(whhP, GIall, b_ih, b_hh, GH, Xt);
    // 5: tail (256 thr)
    tail_kernel<<<TAIL_GRID, 256>>>(Xt, hxs, Xn, MpT, MmT, nMp, nMm, p, ps, r);
    // 6: persistent scan (512 thr)
    scan_persist<<<SCAN_GRID, NTHR>>>(W0t, base, conv0_b, convs_w, convs_b, linT, lin_b,
                                      Xn, MpT, MmT, nMp, nMm, psiT, psi_b,
                                      actor_w, actor_b, critic_w, critic_b,
                                      inter, actions, G, x0, x1, lp, ps, r, out);
    // 7: replicate last step row
    copy_last<<<(Nn * ROW + 255) / 256, 256>>>(out, out_size);
}

// round 16
// speedup vs baseline: 2.3371x; 2.3371x over previous
#include <cuda_runtime.h>
#include <math.h>

#define Hh 256
#define Ss 64
#define ANa 16
#define Tt 32
#define Nn 64
#define HGg 770   // 2 + 3*H
#define G3 2310   // 3*HG
#define ROW 338   // 1+AN+1+H+S
#define KP 832    // padded GRU K (4*208)
#define XSTEP (KP*Nn)
#define GSTEP (G3*Nn)
#define NTHR 256
#define GRU_GRID 148
#define SCAN_GRID 128
#define TAIL_GRID 128

// ---------------- scratch ----------------
__device__ float g_GIvT[G3 * 32];            // [j'][v]
__device__ float g_GIall[Ss * G3 * Nn];      // [s][j'][n]
__device__ float g_GH[4 * G3 * Nn];          // GRU split-K partials [ks][j'][n]
__device__ float g_whhP[G3 * KP];            // padded w_hh [2310][832]
__device__ float g_Xt[Ss * KP * Nn];         // GRU out k-major [s][j(832)][n]
__device__ float g_Xn[Ss * Nn * HGg];        // [s][n][j]
__device__ float g_MpT[Nn * 256 * 64];       // [n][h][sp]
__device__ float g_MmT[Nn * 256 * 64];
__device__ float g_W0t[2048 * 256];
__device__ float g_linT[256 * 16384];
__device__ float g_psiT[16 * 256 * 256];
__device__ float g_p[Nn * Ss];
__device__ float g_ps[Nn * Ss];
__device__ float g_nMp[Nn * Ss];
__device__ float g_nMm[Nn * Ss];
__device__ float g_r[Nn * 256];
__device__ float g_G[4 * 64 * 2048];         // W0 partials Gt[ks][n][j]
__device__ float g_x0[4096 * 256];
__device__ float g_x1[4096 * 256];
__device__ float g_lp[32 * Nn * 256];        // lin split-K partials [ks][n][o]
__device__ unsigned g_bar1, g_bar2, g_bar3;

// ---------------- sync primitives ----------------
__device__ __forceinline__ unsigned ldacq(unsigned* p)
{
    unsigned v;
    asm volatile("ld.acquire.gpu.u32 %0, [%1];" : "=r"(v) : "l"(p) : "memory");
    return v;
}
__device__ __forceinline__ void redrel(unsigned* p, unsigned v)
{
    asm volatile("red.release.gpu.add.u32 [%0], %1;" :: "l"(p), "r"(v) : "memory");
}
__device__ __forceinline__ void gsync(unsigned* bar, unsigned& target)
{
    __syncthreads();
    if (threadIdx.x == 0) {
        redrel(bar, 1u);
        while (ldacq(bar) < target) __nanosleep(64);
    }
    __syncthreads();
    target += gridDim.x;
}

// ---------------- fast transcendentals (MUFU-based, saturation-safe) ----------------
__device__ __forceinline__ float fsigmoid(float x)
{
    return 1.f / (1.f + __expf(-x));
}
__device__ __forceinline__ float ftanh(float x)
{
    float t = __expf(2.f * x);          // inf for large x, 0 for very negative
    return 1.f - 2.f / (t + 1.f);       // -> 1 / -1 at the limits, no NaN
}

// ---------------- f32x2 helpers ----------------
__device__ __forceinline__ unsigned long long pack2(float x)
{
    unsigned long long r;
    asm("mov.b64 %0, {%1, %1};" : "=l"(r) : "r"(__float_as_uint(x)));
    return r;
}
__device__ __forceinline__ void fma2(unsigned long long& d, unsigned long long a, unsigned long long b)
{
    asm("fma.rn.f32x2 %0, %1, %2, %0;" : "+l"(d) : "l"(a), "l"(b));
}
__device__ __forceinline__ float2 unpk(unsigned long long v)
{
    unsigned a, b;
    asm("mov.b64 {%0, %1}, %2;" : "=r"(a), "=r"(b) : "l"(v));
    float2 r; r.x = __uint_as_float(a); r.y = __uint_as_float(b);
    return r;
}

// ---------------- shared pools ----------------
struct SP128 { float As[2][16][132]; float Bs[2][16][72]; };
struct SP64  { float As[2][16][68];  float Bs[2][16][72]; };
struct HeadS {
    float s_sm[256]; float e_sm[256]; float red[256]; float red2[256];
    float logit[16]; float probs[16]; float ps_sm[64]; float pn_sm[64];
    float v; float enorm;
};
struct CPool { float bs[512]; float Gs[512]; };
struct TPool { float t1[64][65]; float t2[64][65]; };
struct StepA { float pv[64]; float psv[64]; };
union SUscan { SP128 g; SP64 g64; HeadS h; CPool c; };
union SUtail { TPool t; StepA a; };

// ---------------- 128x64 tile GEMM, FFMA2 (256 thr) ----------------
__device__ void tile128(SP128& sp,
                        const float* __restrict__ A, int lda,
                        const float* __restrict__ B, int ldb,
                        float* __restrict__ C, int ldc,
                        int m0, int n0, int kb, int kc,
                        const float* __restrict__ bias, bool relu)
{
    const int tid = threadIdx.x;
    const int am = tid >> 1, ak = (tid & 1) * 8;
    const int bn = tid >> 2, bk4 = (tid & 3) * 4;
    const int ty = tid >> 4, tx = tid & 15;
    const int nk = kc >> 4;
    float4 pa0, pa1, pb;

    auto ldg = [&](int kt) {
        int k0 = kb + kt * 16;
        const float* ap = A + (size_t)(m0 + am) * lda + k0 + ak;
        pa0 = *(const float4*)ap;
        pa1 = *(const float4*)(ap + 4);
        pb  = *(const float4*)(B + (size_t)(n0 + bn) * ldb + k0 + bk4);
    };
    auto sts = [&](int buf) {
        sp.As[buf][ak + 0][am] = pa0.x; sp.As[buf][ak + 1][am] = pa0.y;
        sp.As[buf][ak + 2][am] = pa0.z; sp.As[buf][ak + 3][am] = pa0.w;
        sp.As[buf][ak + 4][am] = pa1.x; sp.As[buf][ak + 5][am] = pa1.y;
        sp.As[buf][ak + 6][am] = pa1.z; sp.As[buf][ak + 7][am] = pa1.w;
        sp.Bs[buf][bk4 + 0][bn] = pb.x; sp.Bs[buf][bk4 + 1][bn] = pb.y;
        sp.Bs[buf][bk4 + 2][bn] = pb.z; sp.Bs[buf][bk4 + 3][bn] = pb.w;
    };

    unsigned long long acc[4][4];
    #pragma unroll
    for (int i = 0; i < 4; i++)
        #pragma unroll
        for (int j = 0; j < 4; j++) acc[i][j] = 0ULL;

    ldg(0); sts(0); __syncthreads();
    for (int kt = 0; kt < nk; kt++) {
        if (kt + 1 < nk) ldg(kt + 1);
        const int buf = kt & 1;
        #pragma unroll
        for (int kk = 0; kk < 16; kk++) {
            unsigned long long a2[4], b2[4];
            #pragma unroll
            for (int i = 0; i < 4; i++)
                a2[i] = *(const unsigned long long*)&sp.As[buf][kk][ty * 8 + 2 * i];
            float4 b = *(const float4*)&sp.Bs[buf][kk][tx * 4];
            b2[0] = pack2(b.x); b2[1] = pack2(b.y); b2[2] = pack2(b.z); b2[3] = pack2(b.w);
            #pragma unroll
            for (int i = 0; i < 4; i++)
                #pragma unroll
                for (int j = 0; j < 4; j++) fma2(acc[i][j], a2[i], b2[j]);
        }
        if (kt + 1 < nk) sts(buf ^ 1);
        __syncthreads();
    }

    int gn = n0 + tx * 4;
    float4 bv = make_float4(0.f, 0.f, 0.f, 0.f);
    if (bias) bv = make_float4(bias[gn], bias[gn + 1], bias[gn + 2], bias[gn + 3]);
    #pragma unroll
    for (int i = 0; i < 4; i++) {
        float2 c0 = unpk(acc[i][0]), c1 = unpk(acc[i][1]);
        float2 c2 = unpk(acc[i][2]), c3 = unpk(acc[i][3]);
        float4 r0 = make_float4(c0.x + bv.x, c1.x + bv.y, c2.x + bv.z, c3.x + bv.w);
        float4 r1 = make_float4(c0.y + bv.x, c1.y + bv.y, c2.y + bv.z, c3.y + bv.w);
        if (relu) {
            r0.x = fmaxf(r0.x,0.f); r0.y = fmaxf(r0.y,0.f); r0.z = fmaxf(r0.z,0.f); r0.w = fmaxf(r0.w,0.f);
            r1.x = fmaxf(r1.x,0.f); r1.y = fmaxf(r1.y,0.f); r1.z = fmaxf(r1.z,0.f); r1.w = fmaxf(r1.w,0.f);
        }
        int gm = m0 + ty * 8 + 2 * i;
        *(float4*)&C[(size_t)gm * ldc + gn] = r0;
        *(float4*)&C[(size_t)(gm + 1) * ldc + gn] = r1;
    }
    __syncthreads();
}

// ---------------- 64x64 tile, B k-major [K][64] (GRU, 256 thr) ----------------
__device__ void tile64k(SP64& sp,
                        const float* __restrict__ A, int lda,
                        const float* __restrict__ B,
                        float* __restrict__ C, int ldc,
                        int M, int m0, int kb, int kc)
{
    const int tid = threadIdx.x;
    const int am = tid >> 2, ak4 = (tid & 3) * 4;
    const int bk = tid >> 4, bn4 = (tid & 15) * 4;
    const int ty = tid >> 4, tx = tid & 15;
    const int nk = kc >> 4;
    const float4 z4 = make_float4(0.f, 0.f, 0.f, 0.f);
    float4 pa, pb;

    auto ldg = [&](int kt) {
        int k0 = kb + kt * 16;
        pa = (m0 + am < M) ? *(const float4*)(A + (size_t)(m0 + am) * lda + k0 + ak4) : z4;
        pb = *(const float4*)(B + (size_t)(k0 + bk) * 64 + bn4);
    };
    auto sts = [&](int buf) {
        sp.As[buf][ak4 + 0][am] = pa.x; sp.As[buf][ak4 + 1][am] = pa.y;
        sp.As[buf][ak4 + 2][am] = pa.z; sp.As[buf][ak4 + 3][am] = pa.w;
        *(float4*)&sp.Bs[buf][bk][bn4] = pb;
    };

    unsigned long long acc[2][4];
    #pragma unroll
    for (int i = 0; i < 2; i++)
        #pragma unroll
        for (int j = 0; j < 4; j++) acc[i][j] = 0ULL;

    ldg(0); sts(0); __syncthreads();
    for (int kt = 0; kt < nk; kt++) {
        if (kt + 1 < nk) ldg(kt + 1);
        const int buf = kt & 1;
        #pragma unroll
        for (int kk = 0; kk < 16; kk++) {
            unsigned long long a2[2], b2[4];
            a2[0] = *(const unsigned long long*)&sp.As[buf][kk][ty * 4];
            a2[1] = *(const unsigned long long*)&sp.As[buf][kk][ty * 4 + 2];
            float4 b = *(const float4*)&sp.Bs[buf][kk][tx * 4];
            b2[0] = pack2(b.x); b2[1] = pack2(b.y); b2[2] = pack2(b.z); b2[3] = pack2(b.w);
            #pragma unroll
            for (int i = 0; i < 2; i++)
                #pragma unroll
                for (int j = 0; j < 4; j++) fma2(acc[i][j], a2[i], b2[j]);
        }
        if (kt + 1 < nk) sts(buf ^ 1);
        __syncthreads();
    }

    int gn = tx * 4;
    #pragma unroll
    for (int i = 0; i < 2; i++) {
        float2 c0 = unpk(acc[i][0]), c1 = unpk(acc[i][1]);
        float2 c2 = unpk(acc[i][2]), c3 = unpk(acc[i][3]);
        int gm = m0 + ty * 4 + 2 * i;
        if (gm < M)
            *(float4*)&C[(size_t)gm * ldc + gn] = make_float4(c0.x, c1.x, c2.x, c3.x);
        if (gm + 1 < M)
            *(float4*)&C[(size_t)(gm + 1) * ldc + gn] = make_float4(c0.y, c1.y, c2.y, c3.y);
    }
    __syncthreads();
}

// ---------------- 64x64 tile: A fixed 64 rows [64][lda], B [N][ldb] (256 thr) ----------------
__device__ void tile64n(SP64& sp,
                        const float* __restrict__ A, int lda,
                        const float* __restrict__ B, int ldb,
                        float* __restrict__ C, int ldc,
                        int n0, int kb, int kc)
{
    const int tid = threadIdx.x;
    const int am = tid >> 2, ak4 = (tid & 3) * 4;
    const int bn = tid >> 2, bk4 = (tid & 3) * 4;
    const int ty = tid >> 4, tx = tid & 15;
    const int nk = kc >> 4;
    float4 pa, pb;

    auto ldg = [&](int kt) {
        int k0 = kb + kt * 16;
        pa = *(const float4*)(A + (size_t)am * lda + k0 + ak4);
        pb = *(const float4*)(B + (size_t)(n0 + bn) * ldb + k0 + bk4);
    };
    auto sts = [&](int buf) {
        sp.As[buf][ak4 + 0][am] = pa.x; sp.As[buf][ak4 + 1][am] = pa.y;
        sp.As[buf][ak4 + 2][am] = pa.z; sp.As[buf][ak4 + 3][am] = pa.w;
        sp.Bs[buf][bk4 + 0][bn] = pb.x; sp.Bs[buf][bk4 + 1][bn] = pb.y;
        sp.Bs[buf][bk4 + 2][bn] = pb.z; sp.Bs[buf][bk4 + 3][bn] = pb.w;
    };

    unsigned long long acc[2][4];
    #pragma unroll
    for (int i = 0; i < 2; i++)
        #pragma unroll
        for (int j = 0; j < 4; j++) acc[i][j] = 0ULL;

    ldg(0); sts(0); __syncthreads();
    for (int kt = 0; kt < nk; kt++) {
        if (kt + 1 < nk) ldg(kt + 1);
        const int buf = kt & 1;
        #pragma unroll
        for (int kk = 0; kk < 16; kk++) {
            unsigned long long a2[2], b2[4];
            a2[0] = *(const unsigned long long*)&sp.As[buf][kk][ty * 4];
            a2[1] = *(const unsigned long long*)&sp.As[buf][kk][ty * 4 + 2];
            float4 b = *(const float4*)&sp.Bs[buf][kk][tx * 4];
            b2[0] = pack2(b.x); b2[1] = pack2(b.y); b2[2] = pack2(b.z); b2[3] = pack2(b.w);
            #pragma unroll
            for (int i = 0; i < 2; i++)
                #pragma unroll
                for (int j = 0; j < 4; j++) fma2(acc[i][j], a2[i], b2[j]);
        }
        if (kt + 1 < nk) sts(buf ^ 1);
        __syncthreads();
    }

    int gn = n0 + tx * 4;
    #pragma unroll
    for (int i = 0; i < 2; i++) {
        float2 c0 = unpk(acc[i][0]), c1 = unpk(acc[i][1]);
        float2 c2 = unpk(acc[i][2]), c3 = unpk(acc[i][3]);
        int gm = ty * 4 + 2 * i;
        *(float4*)&C[(size_t)gm * ldc + gn] = make_float4(c0.x, c1.x, c2.x, c3.x);
        *(float4*)&C[(size_t)(gm + 1) * ldc + gn] = make_float4(c0.y, c1.y, c2.y, c3.y);
    }
    __syncthreads();
}

// ---------------- prep: barrier reset + all weight re-layouts ----------------
#define EW0 524288    // W0t
#define EW1 4194304   // linT
#define EW2 1048576   // psiT
#define EW3 1921920   // whhP
#define EW4 253952    // Xt pad zero
#define EWT (EW0+EW1+EW2+EW3+EW4)

__global__ void prep(const float* __restrict__ conv0_w, const float* __restrict__ lin_w,
                     const float* __restrict__ psi_w, const float* __restrict__ w_hh,
                     float* __restrict__ W0t, float* __restrict__ linT,
                     float* __restrict__ psiT, float* __restrict__ whhP,
                     float* __restrict__ Xt)
{
    const int tid = threadIdx.x;
    if (blockIdx.x == 0 && tid < 3) {
        if (tid == 0) g_bar1 = 0;
        else if (tid == 1) g_bar2 = 0;
        else g_bar3 = 0;
    }
    int idx = blockIdx.x * 256 + tid;
    const int stride = gridDim.x * 256;
    for (; idx < EWT; idx += stride) {
        int e = idx;
        if (e < EW0) {
            int h = e & 255, j = e >> 8;
            int o = j >> 3, d = j & 7;
            W0t[e] = conv0_w[o * 2048 + h * 8 + d];
        } else if ((e -= EW0) < EW1) {
            int c = e & 255, pp = (e >> 8) & 63, o = e >> 14;
            linT[e] = lin_w[(size_t)o * 16384 + c * 64 + pp];
        } else if ((e -= EW1) < EW2) {
            int o = e & 255, h = (e >> 8) & 255, a = e >> 16;
            psiT[e] = psi_w[(size_t)o * 4096 + h * 16 + a];
        } else if ((e -= EW2) < EW3) {
            int k = e % KP, j = e / KP;
            whhP[e] = (k < HGg) ? w_hh[j * HGg + k] : 0.f;
        } else {
            e -= EW3;
            int n = e & 63, jj = (e >> 6) % (KP - HGg), s = e / ((KP - HGg) * Nn);
            Xt[(size_t)s * XSTEP + (size_t)(HGg + jj) * 64 + n] = 0.f;
        }
    }
}

// =========== standalone SGEMM (GIvT only) ===========
__global__ void __launch_bounds__(256, 2)
sg(const float* __restrict__ A, int lda,
   const float* __restrict__ B, int ldb,
   float* __restrict__ C, int M, int N, int K)
{
    __shared__ float As[2][16][132];
    __shared__ float Bs[2][16][68];
    const int tid = threadIdx.x;
    const int m0 = blockIdx.x * 128;
    const int nk = K >> 4;
    const int am = tid >> 1, ak = (tid & 1) * 8;
    const int bn = tid >> 2, bk4 = (tid & 3) * 4;
    const int ty = tid >> 4, tx = tid & 15;
    float4 pa0, pa1, pb;
    const float4 z4 = make_float4(0.f, 0.f, 0.f, 0.f);

    auto ldg = [&](int kt) {
        int k0 = kt * 16;
        if (m0 + am < M) {
            const float* ap = A + (size_t)(m0 + am) * lda + k0 + ak;
            pa0 = *(const float4*)ap;
            pa1 = *(const float4*)(ap + 4);
        } else { pa0 = z4; pa1 = z4; }
        pb = (bn < N) ? *(const float4*)(B + (size_t)bn * ldb + k0 + bk4) : z4;
    };
    auto sts = [&](int buf) {
        As[buf][ak + 0][am] = pa0.x; As[buf][ak + 1][am] = pa0.y;
        As[buf][ak + 2][am] = pa0.z; As[buf][ak + 3][am] = pa0.w;
        As[buf][ak + 4][am] = pa1.x; As[buf][ak + 5][am] = pa1.y;
        As[buf][ak + 6][am] = pa1.z; As[buf][ak + 7][am] = pa1.w;
        Bs[buf][bk4 + 0][bn] = pb.x; Bs[buf][bk4 + 1][bn] = pb.y;
        Bs[buf][bk4 + 2][bn] = pb.z; Bs[buf][bk4 + 3][bn] = pb.w;
    };

    float acc[8][4];
    #pragma unroll
    for (int i = 0; i < 8; i++)
        #pragma unroll
        for (int j = 0; j < 4; j++) acc[i][j] = 0.f;

    ldg(0); sts(0); __syncthreads();
    for (int kt = 0; kt < nk; kt++) {
        if (kt + 1 < nk) ldg(kt + 1);
        const int buf = kt & 1;
        #pragma unroll
        for (int kk = 0; kk < 16; kk++) {
            float4 a0 = *(const float4*)&As[buf][kk][ty * 8];
            float4 a1 = *(const float4*)&As[buf][kk][ty * 8 + 4];
            float4 b  = *(const float4*)&Bs[buf][kk][tx * 4];
            float av[8] = {a0.x, a0.y, a0.z, a0.w, a1.x, a1.y, a1.z, a1.w};
            float bv[4] = {b.x, b.y, b.z, b.w};
            #pragma unroll
            for (int i = 0; i < 8; i++)
                #pragma unroll
                for (int j = 0; j < 4; j++) acc[i][j] += av[i] * bv[j];
        }
        if (kt + 1 < nk) sts(buf ^ 1);
        __syncthreads();
    }
    #pragma unroll
    for (int i = 0; i < 8; i++) {
        int gm = m0 + ty * 8 + i;
        if (gm >= M) continue;
        int gn = tx * 4;
        #pragma unroll
        for (int j = 0; j < 4; j++)
            if (gn + j < N) C[(size_t)gm * N + gn + j] = acc[i][j];
    }
}

__global__ void gather_gi(const float* __restrict__ GIvT, const int* __restrict__ subtasks,
                          float* __restrict__ GIall)
{
    int s = blockIdx.x;
    int idx = blockIdx.y * 256 + threadIdx.x;
    if (idx >= G3 * 64) return;
    int jp = idx >> 6, n = idx & 63;
    int v = subtasks[n * Ss + s];
    GIall[(size_t)s * GSTEP + idx] = GIvT[jp * 32 + v];
}

// ---------------- persistent GRU (barrier form, distributed gate, fast transcendentals) ----------------
__global__ void __launch_bounds__(NTHR, 1)
gru_persist(const float* __restrict__ whhP, const float* __restrict__ GIall,
            const float* __restrict__ b_ih, const float* __restrict__ b_hh,
            float* __restrict__ GH, float* __restrict__ Xt)
{
    __shared__ SP64 sp;
    unsigned target = gridDim.x;
    const int bid = blockIdx.x;
    const int tid = threadIdx.x;
    for (int s = 0; s < Ss; s++) {
        if (s > 0) {
            int mt = bid % 37, ks = bid / 37;
            tile64k(sp, whhP, KP, Xt + (size_t)(s - 1) * XSTEP,
                    GH + (size_t)ks * GSTEP, 64, G3, mt * 64, ks * 208, 208);
            gsync(&g_bar1, target);
        }
        for (int idx = bid * NTHR + tid; idx < HGg * Nn; idx += gridDim.x * NTHR) {
            int j = idx >> 6, n = idx & 63;
            const float* gia = GIall + (size_t)s * GSTEP;
            float gir = gia[(size_t)j * 64 + n]             + b_ih[j];
            float giz = gia[(size_t)(j + HGg) * 64 + n]     + b_ih[HGg + j];
            float gin = gia[(size_t)(j + 2 * HGg) * 64 + n] + b_ih[2 * HGg + j];
            float ghr = b_hh[j], ghz = b_hh[HGg + j], ghn = b_hh[2 * HGg + j];
            float hprev = 0.f;
            if (s > 0) {
                #pragma unroll
                for (int ks = 0; ks < 4; ks++) {
                    const float* g = GH + (size_t)ks * GSTEP;
                    ghr += g[(size_t)j * 64 + n];
                    ghz += g[(size_t)(j + HGg) * 64 + n];
                    ghn += g[(size_t)(j + 2 * HGg) * 64 + n];
                }
                hprev = Xt[(size_t)(s - 1) * XSTEP + (size_t)j * 64 + n];
            }
            float r = fsigmoid(gir + ghr);
            float z = fsigmoid(giz + ghz);
            float nn = ftanh(gin + r * ghn);
            Xt[(size_t)s * XSTEP + (size_t)j * 64 + n] = (1.f - z) * nn + z * hprev;
        }
        gsync(&g_bar1, target);
    }
}

// ---------------- tail ----------------
__global__ void __launch_bounds__(NTHR, 1)
tail_kernel(const float* __restrict__ Xt, const float* __restrict__ hxs,
            float* __restrict__ Xn, float* __restrict__ MpT, float* __restrict__ MmT,
            float* __restrict__ nMp, float* __restrict__ nMm,
            float* __restrict__ p, float* __restrict__ ps, float* __restrict__ r)
{
    __shared__ SUtail su;
    __shared__ int anynz;
    unsigned target = gridDim.x;
    const int bid = blockIdx.x;
    const int tid = threadIdx.x;

    for (int job = bid; job < Ss * 13; job += gridDim.x) {
        int s = job / 13, j0 = (job % 13) * 64;
        for (int pq = 0; pq < 16; pq++) {
            int e = pq * 256 + tid;
            int jj = e >> 6, nn = e & 63;
            if (j0 + jj < HGg)
                su.t.t1[jj][nn] = Xt[(size_t)s * XSTEP + (size_t)(j0 + jj) * 64 + nn];
        }
        __syncthreads();
        for (int pq = 0; pq < 16; pq++) {
            int e = pq * 256 + tid;
            int nn = e >> 6, jj = e & 63;
            if (j0 + jj < HGg)
                Xn[(size_t)(s * Nn + nn) * HGg + j0 + jj] = su.t.t1[jj][nn];
        }
        __syncthreads();
    }
    gsync(&g_bar3, target);

    for (int job = bid; job < 256; job += gridDim.x) {
        int n = job >> 2, h0 = (job & 3) * 64;
        for (int pq = 0; pq < 16; pq++) {
            int e = pq * 256 + tid;
            int sp = e >> 6, h = e & 63;
            const float* row = Xn + (size_t)(sp * Nn + n) * HGg;
            su.t.t1[sp][h] = row[2 + 2 * Hh + h0 + h];
            su.t.t2[sp][h] = row[2 + Hh + h0 + h];
        }
        __syncthreads();
        for (int pq = 0; pq < 16; pq++) {
            int e = pq * 256 + tid;
            int h = e >> 6, sp = e & 63;
            MpT[((size_t)n * 256 + h0 + h) * 64 + sp] = su.t.t1[sp][h];
            MmT[((size_t)n * 256 + h0 + h) * 64 + sp] = su.t.t2[sp][h];
        }
        __syncthreads();
    }
    if (bid < 64) {
        const int n = bid;
        if (tid == 0) anynz = 0;
        __syncthreads();
        int local = 0;
        for (int i = tid; i < ROW; i += NTHR)
            if (hxs[n * ROW + i] != 0.f) local = 1;
        if (local) atomicOr(&anynz, 1);
        __syncthreads();
        bool newep = (anynz == 0);
        if (tid < Ss) {
            float p0 = Xn[(size_t)(tid * Nn + n) * HGg + 1];
            p[n * Ss + tid] = newep ? p0 : hxs[n * ROW + 1 + ANa + 1 + Hh + tid];
        }
    }
    gsync(&g_bar3, target);

    if (bid < 16) {
        int idx = bid * 256 + tid;
        int n = idx >> 6, sp = idx & 63;
        const float* bp = MpT + (size_t)n * 256 * 64 + sp;
        const float* bm = MmT + (size_t)n * 256 * 64 + sp;
        float ap = 0.f, am = 0.f;
        #pragma unroll 8
        for (int h = 0; h < 256; h++) {
            float x = bp[h * 64]; ap += x * x;
            float y = bm[h * 64]; am += y * y;
        }
        nMp[idx] = sqrtf(ap);
        nMm[idx] = sqrtf(am);
    } else if (bid >= 64) {
        const int n = bid - 64;
        if (tid < 64) su.a.pv[tid] = p[n * 64 + tid];
        __syncthreads();
        if (tid == 0) {
            float m = su.a.pv[0];
            for (int i = 1; i < 64; i++) m = fmaxf(m, su.a.pv[i]);
            float sum = 0.f;
            for (int i = 0; i < 64; i++) { float e = __expf(su.a.pv[i] - m); su.a.psv[i] = e; sum += e; }
            float inv = 1.f / sum;
            for (int i = 0; i < 64; i++) su.a.psv[i] *= inv;
        }
        __syncthreads();
        if (tid < 64) ps[n * 64 + tid] = su.a.psv[tid];
        float acc = 0.f;
        for (int s = 0; s < 64; s++)
            acc += su.a.psv[s] * Xn[(size_t)(s * Nn + n) * HGg + 2 + tid];
        r[n * 256 + tid] = acc;
    }
}

// ---------------- head body ----------------
__device__ void head_body(HeadS& hs, int n,
    const float* __restrict__ lp, const float* __restrict__ lin_b,
    float* __restrict__ ps_buf,
    const float* __restrict__ X, const float* __restrict__ MpT, const float* __restrict__ MmT,
    const float* __restrict__ nMp, const float* __restrict__ nMm,
    const float* __restrict__ psiT, const float* __restrict__ psi_b,
    const float* __restrict__ actor_w, const float* __restrict__ actor_b,
    const float* __restrict__ critic_w, const float* __restrict__ critic_b,
    const float* __restrict__ inter_t, const int* __restrict__ act_t,
    float* __restrict__ r_out, float* __restrict__ out_t)
{
    int tid = threadIdx.x;
    {
        float sv = lin_b[tid];
        #pragma unroll 4
        for (int ks = 0; ks < 32; ks++) sv += lp[(size_t)ks * 16384 + n * 256 + tid];
        hs.s_sm[tid] = fmaxf(sv, 0.f);
    }
    if (tid < 64) hs.ps_sm[tid] = ps_buf[n * 64 + tid];
    __syncthreads();
    int a = act_t[n];
    {
        float acc = psi_b[tid];
        const float* P = psiT + (size_t)a * 65536;
        for (int h = 0; h < 256; h++) acc += P[h * 256 + tid] * hs.s_sm[h];
        hs.e_sm[tid] = acc;
        hs.red[tid] = acc * acc;
    }
    __syncthreads();
    for (int off = 128; off > 0; off >>= 1) {
        if (tid < off) hs.red[tid] += hs.red[tid + off];
        __syncthreads();
    }
    if (tid == 0) hs.enorm = sqrtf(hs.red[0]);
    if (tid < 16) {
        float acc = actor_b[tid];
        for (int h = 0; h < 256; h++) acc += actor_w[tid * 256 + h] * hs.s_sm[h];
        hs.logit[tid] = acc;
    } else if (tid == 32) {
        float acc = critic_b[0];
        for (int h = 0; h < 256; h++) acc += critic_w[h] * hs.s_sm[h];
        hs.v = acc;
    }
    __syncthreads();
    if (tid == 0) {
        float pr[16], nonzero[16];
        float mx = hs.logit[0];
        for (int aa = 1; aa < 16; aa++) mx = fmaxf(mx, hs.logit[aa]);
        float sum = 0.f;
        for (int aa = 0; aa < 16; aa++) { pr[aa] = __expf(hs.logit[aa] - mx); sum += pr[aa]; }
        float inv = 1.f / sum;
        float nzsum = 0.f;
        for (int aa = 0; aa < 16; aa++) {
            float nz = (aa < 5) ? 1.f : inter_t[n * 11 + aa - 5];
            nonzero[aa] = nz; nzsum += fabsf(nz);
        }
        float psum = 0.f;
        for (int aa = 0; aa < 16; aa++) { pr[aa] = pr[aa] * inv * nonzero[aa]; psum += pr[aa]; }
        float deficit = 1.f - psum;
        float nzinv = 1.f / fmaxf(nzsum, 1e-12f);
        float csum = 0.f;
        for (int aa = 0; aa < 16; aa++) {
            float v2 = pr[aa] + nonzero[aa] * nzinv * deficit;
            v2 = fminf(fmaxf(v2, 0.f), 1.f);
            pr[aa] = v2; csum += fabsf(v2);
        }
        float cinv = 1.f / fmaxf(csum, 1e-12f);
        for (int aa = 0; aa < 16; aa++) hs.probs[aa] = pr[aa] * cinv;
    }
    __syncthreads();
    {
        int sp = tid & 63, hq = tid >> 6;
        const float* bp = MpT + ((size_t)n * 256 + hq * 64) * 64 + sp;
        const float* bm = MmT + ((size_t)n * 256 + hq * 64) * 64 + sp;
        float np = 0.f, nm = 0.f;
        #pragma unroll 8
        for (int h = 0; h < 64; h++) {
            float e = hs.e_sm[hq * 64 + h];
            np += e * bp[h * 64];
            nm += e * bm[h * 64];
        }
        hs.red[tid] = np; hs.red2[tid] = nm;
    }
    __syncthreads();
    if (tid < 64) {
        int sp = tid;
        float np = hs.red[sp] + hs.red[64 + sp] + hs.red[128 + sp] + hs.red[192 + sp];
        float nm = hs.red2[sp] + hs.red2[64 + sp] + hs.red2[128 + sp] + hs.red2[192 + sp];
        float en = hs.enorm;
        float c = X[(size_t)(sp * Nn + n) * HGg];
        float cosp = np / fmaxf(en * nMp[n * 64 + sp], 1e-8f);
        float cosm = nm / fmaxf(en * nMm[n * 64 + sp], 1e-8f);
        float pn = hs.ps_sm[sp] + c * cosp - c * cosm;
        hs.pn_sm[sp] = pn;
        out_t[(size_t)n * ROW + 1 + ANa + 1 + Hh + sp] = pn;
    }
    out_t[(size_t)n * ROW + 18 + tid] = hs.s_sm[tid];
    if (tid < 16) out_t[(size_t)n * ROW + 1 + tid] = hs.probs[tid];
    if (tid == 0) {
        out_t[(size_t)n * ROW + 0] = (float)a;
        out_t[(size_t)n * ROW + 17] = hs.v;
    }
    __syncthreads();
    if (tid == 0) {
        float m = hs.pn_sm[0];
        for (int i = 1; i < 64; i++) m = fmaxf(m, hs.pn_sm[i]);
        float sum = 0.f;
        for (int i = 0; i < 64; i++) { float e = __expf(hs.pn_sm[i] - m); hs.ps_sm[i] = e; sum += e; }
        float inv = 1.f / sum;
        for (int i = 0; i < 64; i++) hs.ps_sm[i] *= inv;
    }
    __syncthreads();
    if (tid < 64) ps_buf[n * 64 + tid] = hs.ps_sm[tid];
    float acc = 0.f;
    for (int s = 0; s < 64; s++)
        acc += hs.ps_sm[s] * X[(size_t)(s * Nn + n) * HGg + 2 + tid];
    r_out[n * 256 + tid] = acc;
    __syncthreads();
}

// ---------------- persistent scan ----------------
__global__ void __launch_bounds__(NTHR, 1)
scan_persist(const float* __restrict__ W0t, const float* __restrict__ base,
             const float* __restrict__ conv0_b,
             const float* __restrict__ convs_w, const float* __restrict__ convs_b,
             const float* __restrict__ linT, const float* __restrict__ lin_b,
             const float* __restrict__ Xn, const float* __restrict__ MpT,
             const float* __restrict__ MmT,
             const float* __restrict__ nMp, const float* __restrict__ nMm,
             const float* __restrict__ psiT, const float* __restrict__ psi_b,
             const float* __restrict__ actor_w, const float* __restrict__ actor_b,
             const float* __restrict__ critic_w, const float* __restrict__ critic_b,
             const float* __restrict__ inter, const int* __restrict__ actions,
             float* __restrict__ G, float* __restrict__ x0, float* __restrict__ x1,
             float* __restrict__ lp, float* __restrict__ ps, float* __restrict__ r,
             float* __restrict__ out)
{
    __shared__ SUscan su;
    unsigned target = gridDim.x;
    const int bid = blockIdx.x;
    const int tid = threadIdx.x;

    for (int t = 0; t < Tt; t++) {
        // P1: Gt[ks][n][j] = r . W0t^T  (32 jt x 4 ks)
        {
            int jt = bid & 31, ks = bid >> 5;
            tile64n(su.g64, r, 256, W0t, 256,
                    G + (size_t)ks * 64 * 2048, 2048, jt * 64, ks * 64, 64);
        }
        gsync(&g_bar2, target);

        // P2: conv0 dot-8 collapse -> x0[(n*64+p)][o]
        const float* base_t = base + (size_t)t * Nn * 512;
        for (int job = bid; job < 256; job += gridDim.x) {
            int n = job >> 2, o0 = (job & 3) * 64;
            for (int e = tid; e < 512; e += 256) su.c.bs[e] = base_t[n * 512 + e];
            for (int e = tid; e < 512; e += 256) {
                int j = o0 * 8 + e;
                float v = 0.f;
                #pragma unroll
                for (int ks = 0; ks < 4; ks++) v += G[(size_t)ks * 131072 + n * 2048 + j];
                su.c.Gs[e] = v;
            }
            __syncthreads();
            int o_l = tid & 63;
            int pg = tid >> 6;
            float bias = conv0_b[o0 + o_l];
            for (int k = 0; k < 16; k++) {
                int pp = pg * 16 + k;
                float acc = bias;
                #pragma unroll
                for (int d = 0; d < 8; d++) acc += su.c.Gs[o_l * 8 + d] * su.c.bs[d * 64 + pp];
                x0[((size_t)n * 64 + pp) * 256 + o0 + o_l] = fmaxf(acc, 0.f);
            }
            __syncthreads();
        }
        gsync(&g_bar2, target);

        // P3: conv1 (32 mt x 4 nt)
        {
            int mt = bid >> 2, nt = bid & 3;
            tile128(su.g, x0, 256, convs_w, 256, x1, 256,
                    mt * 128, nt * 64, 0, 256, convs_b, true);
        }
        gsync(&g_bar2, target);

        // P4: conv2
        {
            int mt = bid >> 2, nt = bid & 3;
            tile128(su.g, x1, 256, convs_w + 65536, 256, x0, 256,
                    mt * 128, nt * 64, 0, 256, convs_b + 256, true);
        }
        gsync(&g_bar2, target);

        // P5: lin partials lp[ks][64][256]  (4 nt x 32 ks)
        {
            int nt = bid & 3, ks = bid >> 2;
            tile64n(su.g64, x0, 16384, linT, 16384,
                    lp + (size_t)ks * 16384, 256, nt * 64, ks * 512, 512);
        }
        gsync(&g_bar2, target);

        // P6: head (folds lin reduce)
        if (bid < 64) {
            head_body(su.h, bid, lp, lin_b, ps, Xn, MpT, MmT, nMp, nMm,
                      psiT, psi_b, actor_w, actor_b, critic_w, critic_b,
                      inter + (size_t)t * Nn * 11, actions + t * Nn,
                      r, out + (size_t)t * Nn * ROW);
        }
        gsync(&g_bar2, target);
    }
}

__global__ void copy_last(float* __restrict__ out, int out_size)
{
    int idx = blockIdx.x * 256 + threadIdx.x;
    if (idx >= Nn * ROW) return;
    int dst = Tt * Nn * ROW + idx;
    if (dst < out_size) out[dst] = out[(Tt - 1) * Nn * ROW + idx];
}

// ---------------- orchestration ----------------
extern "C" void kernel_launch(void* const* d_in, const int* in_sizes, int n_in,
                              void* d_out, int out_size)
{
    const float* base    = (const float*)d_in[0];
    const float* inter   = (const float*)d_in[1];
    const float* hxs     = (const float*)d_in[2];
    const float* emb     = (const float*)d_in[3];
    const float* w_ih    = (const float*)d_in[4];
    const float* w_hh    = (const float*)d_in[5];
    const float* b_ih    = (const float*)d_in[6];
    const float* b_hh    = (const float*)d_in[7];
    const float* conv0_w = (const float*)d_in[8];
    const float* conv0_b = (const float*)d_in[9];
    const float* convs_w = (const float*)d_in[10];
    const float* convs_b = (const float*)d_in[11];
    const float* lin_w   = (const float*)d_in[12];
    const float* lin_b   = (const float*)d_in[13];
    const float* psi_w   = (const float*)d_in[14];
    const float* psi_b   = (const float*)d_in[15];
    const float* actor_w = (const float*)d_in[16];
    const float* actor_b = (const float*)d_in[17];
    const float* critic_w= (const float*)d_in[18];
    const float* critic_b= (const float*)d_in[19];
    const int*   subtasks= (const int*)d_in[20];
    const int*   actions = (const int*)d_in[21];
    float* out = (float*)d_out;

    float *GIvT, *GIall, *GH, *whhP, *Xt, *Xn, *MpT, *MmT, *W0t, *linT, *psiT;
    float *p, *ps, *nMp, *nMm, *r, *G, *x0, *x1, *lp;
    cudaGetSymbolAddress((void**)&GIvT,  g_GIvT);
    cudaGetSymbolAddress((void**)&GIall, g_GIall);
    cudaGetSymbolAddress((void**)&GH,    g_GH);
    cudaGetSymbolAddress((void**)&whhP,  g_whhP);
    cudaGetSymbolAddress((void**)&Xt,    g_Xt);
    cudaGetSymbolAddress((void**)&Xn,    g_Xn);
    cudaGetSymbolAddress((void**)&MpT,   g_MpT);
    cudaGetSymbolAddress((void**)&MmT,   g_MmT);
    cudaGetSymbolAddress((void**)&W0t,   g_W0t);
    cudaGetSymbolAddress((void**)&linT,  g_linT);
    cudaGetSymbolAddress((void**)&psiT,  g_psiT);
    cudaGetSymbolAddress((void**)&p,     g_p);
    cudaGetSymbolAddress((void**)&ps,    g_ps);
    cudaGetSymbolAddress((void**)&nMp,   g_nMp);
    cudaGetSymbolAddress((void**)&nMm,   g_nMm);
    cudaGetSymbolAddress((void**)&r,     g_r);
    cudaGetSymbolAddress((void**)&G,     g_G);
    cudaGetSymbolAddress((void**)&x0,    g_x0);
    cudaGetSymbolAddress((void**)&x1,    g_x1);
    cudaGetSymbolAddress((void**)&lp,    g_lp);

    // 1: prep (barrier reset + all weight re-layouts)
    prep<<<2048, 256>>>(conv0_w, lin_w, psi_w, w_hh, W0t, linT, psiT, whhP, Xt);
    // 2: GIvT GEMM
    sg<<<19, 256>>>(w_ih, 256, emb, 256, GIvT, G3, 32, 256);
    // 3: gather input gates
    gather_gi<<<dim3(Ss, (G3 * 64 + 255) / 256), 256>>>(GIvT, subtasks, GIall);
    // 4: persistent GRU
    gru_persist<<<GRU_GRID, NTHR>>>(whhP, GIall, b_ih, b_hh, GH, Xt);
    // 5: tail
    tail_kernel<<<TAIL_GRID, NTHR>>>(Xt, hxs, Xn, MpT, MmT, nMp, nMm, p, ps, r);
    // 6: persistent scan
    scan_persist<<<SCAN_GRID, NTHR>>>(W0t, base, conv0_b, convs_w, convs_b, linT, lin_b,
                                      Xn, MpT, MmT, nMp, nMm, psiT, psi_b,
                                      actor_w, actor_b, critic_w, critic_b,
                                      inter, actions, G, x0, x1, lp, ps, r, out);
    // 7: replicate last step row
    copy_last<<<(Nn * ROW + 255) / 256, 256>>>(out, out_size);
}